// round 1
// baseline (speedup 1.0000x reference)
#include <cuda_runtime.h>
#include <math.h>

#define H 8192
#define NSPLIT 32
#define ROWS_PER_SPLIT (H / NSPLIT)   // 256

// Scratch (no cudaMalloc allowed)
__device__ float g_h1[H];
__device__ float g_h2[H];
__device__ float g_part[NSPLIT * H];

// ---------------- Layer 1: h1 = relu(state @ W1 + b1) ----------------
// W1 is [42, H] row-major. One thread per output column.
__global__ void k1_layer1(const float* __restrict__ state,
                          const float* __restrict__ W1,
                          const float* __restrict__ b1) {
    __shared__ float s[42];
    int t = threadIdx.x;
    if (t < 42) s[t] = state[t];
    __syncthreads();
    int j = blockIdx.x * blockDim.x + t;
    float acc = b1[j];
    #pragma unroll
    for (int k = 0; k < 42; k++)
        acc = fmaf(s[k], W1[(size_t)k * H + j], acc);
    g_h1[j] = fmaxf(acc, 0.0f);
}

// ---------------- Layer 2 partials: part[s][j] = sum over row-chunk ----------------
// W2 is [H, H] row-major. blockIdx.x: column block (1024 cols via 256 thr * float4),
// blockIdx.y: row split (256 rows). Fully coalesced float4 streaming of W2.
__global__ void k2_gemv(const float* __restrict__ W2) {
    __shared__ float xs[ROWS_PER_SPLIT];
    int t = threadIdx.x;
    int r0 = blockIdx.y * ROWS_PER_SPLIT;
    xs[t] = g_h1[r0 + t];          // blockDim.x == 256 == ROWS_PER_SPLIT
    __syncthreads();

    int c = (blockIdx.x * 256 + t) * 4;
    const float4* W = reinterpret_cast<const float4*>(W2 + (size_t)r0 * H + c);

    float4 acc = make_float4(0.f, 0.f, 0.f, 0.f);
    #pragma unroll 8
    for (int r = 0; r < ROWS_PER_SPLIT; r++) {
        float4 w = W[(size_t)r * (H / 4)];
        float  x = xs[r];
        acc.x = fmaf(x, w.x, acc.x);
        acc.y = fmaf(x, w.y, acc.y);
        acc.z = fmaf(x, w.z, acc.z);
        acc.w = fmaf(x, w.w, acc.w);
    }
    *reinterpret_cast<float4*>(g_part + (size_t)blockIdx.y * H + c) = acc;
}

// ---------------- Reduce partials: h2 = relu(sum_s part[s] + b2) ----------------
__global__ void k3_reduce(const float* __restrict__ b2) {
    int j = blockIdx.x * blockDim.x + threadIdx.x;
    float acc = b2[j];
    #pragma unroll
    for (int s = 0; s < NSPLIT; s++)
        acc += g_part[(size_t)s * H + j];
    g_h2[j] = fmaxf(acc, 0.0f);
}

// ---------------- Head: pen = h2 @ W3 + b3; value + masked softmax ----------------
// W3 is [H, 8] row-major: each row is 8 contiguous floats (two float4 loads).
__global__ void k4_head(const float* __restrict__ state,
                        const float* __restrict__ W3,
                        const float* __restrict__ b3,
                        float* __restrict__ out) {
    __shared__ float red[256][8];
    int t = threadIdx.x;
    float acc[8];
    #pragma unroll
    for (int n = 0; n < 8; n++) acc[n] = 0.0f;

    for (int i = t; i < H; i += 256) {
        float v = g_h2[i];
        float4 w0 = *reinterpret_cast<const float4*>(W3 + (size_t)i * 8);
        float4 w1 = *reinterpret_cast<const float4*>(W3 + (size_t)i * 8 + 4);
        acc[0] = fmaf(v, w0.x, acc[0]);
        acc[1] = fmaf(v, w0.y, acc[1]);
        acc[2] = fmaf(v, w0.z, acc[2]);
        acc[3] = fmaf(v, w0.w, acc[3]);
        acc[4] = fmaf(v, w1.x, acc[4]);
        acc[5] = fmaf(v, w1.y, acc[5]);
        acc[6] = fmaf(v, w1.z, acc[6]);
        acc[7] = fmaf(v, w1.w, acc[7]);
    }
    #pragma unroll
    for (int n = 0; n < 8; n++) red[t][n] = acc[n];
    __syncthreads();

    for (int stride = 128; stride > 0; stride >>= 1) {
        if (t < stride) {
            #pragma unroll
            for (int n = 0; n < 8; n++) red[t][n] += red[t + stride][n];
        }
        __syncthreads();
    }

    if (t == 0) {
        float pen[8];
        #pragma unroll
        for (int n = 0; n < 8; n++) pen[n] = red[0][n] + b3[n];

        float value = pen[7];

        bool legal[7];
        float mx = -INFINITY;
        #pragma unroll
        for (int n = 0; n < 7; n++) {
            legal[n] = (state[n] == 0.0f);
            if (legal[n] && pen[n] > mx) mx = pen[n];
        }
        float e[7];
        float sum = 0.0f;
        #pragma unroll
        for (int n = 0; n < 7; n++) {
            e[n] = legal[n] ? expf(pen[n] - mx) : 0.0f;
            sum += e[n];
        }
        float inv = 1.0f / sum;
        out[0] = value;
        #pragma unroll
        for (int n = 0; n < 7; n++) out[1 + n] = e[n] * inv;
    }
}

extern "C" void kernel_launch(void* const* d_in, const int* in_sizes, int n_in,
                              void* d_out, int out_size) {
    const float* state = (const float*)d_in[0];
    const float* W1    = (const float*)d_in[1];
    const float* b1    = (const float*)d_in[2];
    const float* W2    = (const float*)d_in[3];
    const float* b2    = (const float*)d_in[4];
    const float* W3    = (const float*)d_in[5];
    const float* b3    = (const float*)d_in[6];
    float* out = (float*)d_out;

    k1_layer1<<<H / 256, 256>>>(state, W1, b1);

    dim3 g2(H / (256 * 4), NSPLIT);   // (8, 32) = 256 blocks
    k2_gemv<<<g2, 256>>>(W2);

    k3_reduce<<<H / 256, 256>>>(b2);

    k4_head<<<1, 256>>>(state, W3, b3, out);
}

// round 2
// speedup vs baseline: 1.2764x; 1.2764x over previous
#include <cuda_runtime.h>
#include <math.h>

#define H 8192
#define NSPLIT 32
#define ROWS_PER_SPLIT (H / NSPLIT)   // 256
#define COLBLKS (H / (256 * 4))       // 8

// Scratch (no cudaMalloc allowed)
__device__ float g_part[NSPLIT * H];     // layer-2 partials
__device__ float g_pen_part[NSPLIT * 8]; // head partials

// ---------------- Fused: h1 chunk (recomputed per block) + layer-2 GEMV partials ----
// W1 [42,H], W2 [H,H] row-major.
// blockIdx.x: column block (1024 cols via 256 thr * float4)
// blockIdx.y: row split (256 rows of W2 == 256 h1 values, recomputed here)
__global__ void __launch_bounds__(256) k2_fused(const float* __restrict__ state,
                                                const float* __restrict__ W1,
                                                const float* __restrict__ b1,
                                                const float* __restrict__ W2) {
    __shared__ float s[42];
    __shared__ float xs[ROWS_PER_SPLIT];
    int t = threadIdx.x;
    if (t < 42) s[t] = state[t];
    __syncthreads();

    int r0 = blockIdx.y * ROWS_PER_SPLIT;

    // compute h1[r0 + t] = relu(b1 + sum_k s[k]*W1[k][r0+t])
    {
        float acc = b1[r0 + t];
        #pragma unroll
        for (int k = 0; k < 42; k++)
            acc = fmaf(s[k], __ldg(W1 + (size_t)k * H + r0 + t), acc);
        xs[t] = fmaxf(acc, 0.0f);
    }
    __syncthreads();

    int c = (blockIdx.x * 256 + t) * 4;
    const float4* W = reinterpret_cast<const float4*>(W2 + (size_t)r0 * H + c);

    float4 acc = make_float4(0.f, 0.f, 0.f, 0.f);
    #pragma unroll 8
    for (int r = 0; r < ROWS_PER_SPLIT; r++) {
        float4 w = __ldcs(&W[(size_t)r * (H / 4)]);   // streaming: no L2 reuse possible
        float  x = xs[r];
        acc.x = fmaf(x, w.x, acc.x);
        acc.y = fmaf(x, w.y, acc.y);
        acc.z = fmaf(x, w.z, acc.z);
        acc.w = fmaf(x, w.w, acc.w);
    }
    *reinterpret_cast<float4*>(g_part + (size_t)blockIdx.y * H + c) = acc;
}

// ---------------- Fused: reduce partials -> h2 (in-register) -> pen partials ------
// 32 blocks x 256 threads: thread handles one column j of h2, then its W3 row.
__global__ void __launch_bounds__(256) k3_fused(const float* __restrict__ b2,
                                                const float* __restrict__ W3) {
    __shared__ float red[256][8];
    int t = threadIdx.x;
    int j = blockIdx.x * 256 + t;

    float acc = b2[j];
    #pragma unroll
    for (int sIdx = 0; sIdx < NSPLIT; sIdx++)
        acc += g_part[(size_t)sIdx * H + j];
    float h2 = fmaxf(acc, 0.0f);

    float4 w0 = *reinterpret_cast<const float4*>(W3 + (size_t)j * 8);
    float4 w1 = *reinterpret_cast<const float4*>(W3 + (size_t)j * 8 + 4);
    red[t][0] = h2 * w0.x;
    red[t][1] = h2 * w0.y;
    red[t][2] = h2 * w0.z;
    red[t][3] = h2 * w0.w;
    red[t][4] = h2 * w1.x;
    red[t][5] = h2 * w1.y;
    red[t][6] = h2 * w1.z;
    red[t][7] = h2 * w1.w;
    __syncthreads();

    for (int stride = 128; stride > 0; stride >>= 1) {
        if (t < stride) {
            #pragma unroll
            for (int n = 0; n < 8; n++) red[t][n] += red[t + stride][n];
        }
        __syncthreads();
    }

    if (t < 8) g_pen_part[blockIdx.x * 8 + t] = red[0][t];
}

// ---------------- Final: sum pen partials, bias, value + masked softmax ----------
__global__ void k_final(const float* __restrict__ state,
                        const float* __restrict__ b3,
                        float* __restrict__ out) {
    int t = threadIdx.x;   // one warp
    float pen = 0.0f;
    if (t < 8) {
        pen = b3[t];
        #pragma unroll
        for (int sIdx = 0; sIdx < NSPLIT; sIdx++)
            pen += g_pen_part[sIdx * 8 + t];
    }
    // gather all 8 pen values into every lane via shfl
    float pens[8];
    #pragma unroll
    for (int n = 0; n < 8; n++)
        pens[n] = __shfl_sync(0xFFFFFFFF, pen, n);

    if (t == 0) {
        float value = pens[7];
        bool legal[7];
        float mx = -INFINITY;
        #pragma unroll
        for (int n = 0; n < 7; n++) {
            legal[n] = (state[n] == 0.0f);
            if (legal[n] && pens[n] > mx) mx = pens[n];
        }
        float e[7];
        float sum = 0.0f;
        #pragma unroll
        for (int n = 0; n < 7; n++) {
            e[n] = legal[n] ? expf(pens[n] - mx) : 0.0f;
            sum += e[n];
        }
        float inv = 1.0f / sum;
        out[0] = value;
        #pragma unroll
        for (int n = 0; n < 7; n++) out[1 + n] = e[n] * inv;
    }
}

extern "C" void kernel_launch(void* const* d_in, const int* in_sizes, int n_in,
                              void* d_out, int out_size) {
    const float* state = (const float*)d_in[0];
    const float* W1    = (const float*)d_in[1];
    const float* b1    = (const float*)d_in[2];
    const float* W2    = (const float*)d_in[3];
    const float* b2    = (const float*)d_in[4];
    const float* W3    = (const float*)d_in[5];
    const float* b3    = (const float*)d_in[6];
    float* out = (float*)d_out;

    dim3 g2(COLBLKS, NSPLIT);   // (8, 32) = 256 blocks
    k2_fused<<<g2, 256>>>(state, W1, b1, W2);

    k3_fused<<<NSPLIT, 256>>>(b2, W3);

    k_final<<<1, 32>>>(state, b3, out);
}

// round 3
// speedup vs baseline: 1.3284x; 1.0407x over previous
#include <cuda_runtime.h>
#include <math.h>

#define H 8192
#define NSPLIT 128
#define ROWS_PER_SPLIT (H / NSPLIT)   // 64
#define COLBLKS (H / (256 * 4))       // 8

// Scratch (no cudaMalloc allowed)
__device__ float g_part[NSPLIT * H];     // layer-2 partials (4 MB, lives in L2)
__device__ float g_pen_part[NSPLIT * 8]; // head partials

// ---------------- Fused: h1 chunk (recomputed per block) + layer-2 GEMV partials ----
// W1 [42,H], W2 [H,H] row-major.
// blockIdx.x: column block (1024 cols via 256 thr * float4)
// blockIdx.y: row split (64 rows of W2 == 64 h1 values, recomputed here; W1 hits L2)
__global__ void __launch_bounds__(256, 6) k2_fused(const float* __restrict__ state,
                                                   const float* __restrict__ W1,
                                                   const float* __restrict__ b1,
                                                   const float* __restrict__ W2) {
    __shared__ float s[42];
    __shared__ float xs[ROWS_PER_SPLIT];
    int t = threadIdx.x;
    if (t < 42) s[t] = state[t];
    __syncthreads();

    int r0 = blockIdx.y * ROWS_PER_SPLIT;

    // threads 0..63 compute h1[r0 + t] = relu(b1 + sum_k s[k]*W1[k][r0+t])
    if (t < ROWS_PER_SPLIT) {
        float acc = b1[r0 + t];
        #pragma unroll
        for (int k = 0; k < 42; k++)
            acc = fmaf(s[k], __ldg(W1 + (size_t)k * H + r0 + t), acc);
        xs[t] = fmaxf(acc, 0.0f);
    }
    __syncthreads();

    int c = (blockIdx.x * 256 + t) * 4;
    const float4* W = reinterpret_cast<const float4*>(W2 + (size_t)r0 * H + c);

    float4 acc = make_float4(0.f, 0.f, 0.f, 0.f);
    #pragma unroll 8
    for (int r = 0; r < ROWS_PER_SPLIT; r++) {
        float4 w = __ldcs(&W[(size_t)r * (H / 4)]);   // streaming: no reuse possible
        float  x = xs[r];
        acc.x = fmaf(x, w.x, acc.x);
        acc.y = fmaf(x, w.y, acc.y);
        acc.z = fmaf(x, w.z, acc.z);
        acc.w = fmaf(x, w.w, acc.w);
    }
    *reinterpret_cast<float4*>(g_part + (size_t)blockIdx.y * H + c) = acc;
}

// ---------------- Fused: reduce partials -> h2 (in-register) -> pen partials ------
// 32 blocks x 256 threads: thread handles one column j of h2, then its W3 row.
__global__ void __launch_bounds__(256) k3_fused(const float* __restrict__ b2,
                                                const float* __restrict__ W3) {
    __shared__ float red[256][8];
    int t = threadIdx.x;
    int j = blockIdx.x * 256 + t;

    float acc = b2[j];
    #pragma unroll
    for (int sIdx = 0; sIdx < NSPLIT; sIdx++)
        acc += g_part[(size_t)sIdx * H + j];
    float h2 = fmaxf(acc, 0.0f);

    float4 w0 = *reinterpret_cast<const float4*>(W3 + (size_t)j * 8);
    float4 w1 = *reinterpret_cast<const float4*>(W3 + (size_t)j * 8 + 4);
    red[t][0] = h2 * w0.x;
    red[t][1] = h2 * w0.y;
    red[t][2] = h2 * w0.z;
    red[t][3] = h2 * w0.w;
    red[t][4] = h2 * w1.x;
    red[t][5] = h2 * w1.y;
    red[t][6] = h2 * w1.z;
    red[t][7] = h2 * w1.w;
    __syncthreads();

    for (int stride = 128; stride > 0; stride >>= 1) {
        if (t < stride) {
            #pragma unroll
            for (int n = 0; n < 8; n++) red[t][n] += red[t + stride][n];
        }
        __syncthreads();
    }

    if (t < 8) g_pen_part[blockIdx.x * 8 + t] = red[0][t];
}

// ---------------- Final: sum pen partials over 32 col-blocks, bias, softmax ------
__global__ void k_final(const float* __restrict__ state,
                        const float* __restrict__ b3,
                        float* __restrict__ out) {
    int t = threadIdx.x;   // one warp
    float pen = 0.0f;
    if (t < 8) {
        pen = b3[t];
        #pragma unroll
        for (int sIdx = 0; sIdx < 32; sIdx++)
            pen += g_pen_part[sIdx * 8 + t];
    }
    float pens[8];
    #pragma unroll
    for (int n = 0; n < 8; n++)
        pens[n] = __shfl_sync(0xFFFFFFFF, pen, n);

    if (t == 0) {
        float value = pens[7];
        bool legal[7];
        float mx = -INFINITY;
        #pragma unroll
        for (int n = 0; n < 7; n++) {
            legal[n] = (state[n] == 0.0f);
            if (legal[n] && pens[n] > mx) mx = pens[n];
        }
        float e[7];
        float sum = 0.0f;
        #pragma unroll
        for (int n = 0; n < 7; n++) {
            e[n] = legal[n] ? expf(pens[n] - mx) : 0.0f;
            sum += e[n];
        }
        float inv = 1.0f / sum;
        out[0] = value;
        #pragma unroll
        for (int n = 0; n < 7; n++) out[1 + n] = e[n] * inv;
    }
}

extern "C" void kernel_launch(void* const* d_in, const int* in_sizes, int n_in,
                              void* d_out, int out_size) {
    const float* state = (const float*)d_in[0];
    const float* W1    = (const float*)d_in[1];
    const float* b1    = (const float*)d_in[2];
    const float* W2    = (const float*)d_in[3];
    const float* b2    = (const float*)d_in[4];
    const float* W3    = (const float*)d_in[5];
    const float* b3    = (const float*)d_in[6];
    float* out = (float*)d_out;

    dim3 g2(COLBLKS, NSPLIT);   // (8, 128) = 1024 blocks
    k2_fused<<<g2, 256>>>(state, W1, b1, W2);

    k3_fused<<<32, 256>>>(b2, W3);   // 32 blocks x 256 = 8192 columns

    k_final<<<1, 32>>>(state, b3, out);
}

// round 4
// speedup vs baseline: 1.4936x; 1.1244x over previous
#include <cuda_runtime.h>
#include <math.h>

#define H 8192
#define NSPLIT 64
#define ROWS_PER_SPLIT (H / NSPLIT)   // 128
#define COLBLKS (H / (256 * 4))       // 8
#define UNROLL 8

// Scratch (no cudaMalloc allowed)
__device__ float g_part[NSPLIT * H];     // layer-2 partials (2 MB, lives in L2)
__device__ float g_pen_part[32 * 8];     // head partials

// ---------------- Fused: h1 chunk (recomputed per block) + layer-2 GEMV partials ----
// W1 [42,H], W2 [H,H] row-major.
// blockIdx.x: column block (1024 cols via 256 thr * float4)
// blockIdx.y: row split (128 rows of W2 == 128 h1 values, recomputed here; W1 hits L2)
__global__ void __launch_bounds__(256, 4) k2_fused(const float* __restrict__ state,
                                                   const float* __restrict__ W1,
                                                   const float* __restrict__ b1,
                                                   const float* __restrict__ W2) {
    __shared__ float s[42];
    __shared__ float xs[ROWS_PER_SPLIT];
    int t = threadIdx.x;
    if (t < 42) s[t] = state[t];
    __syncthreads();

    int r0 = blockIdx.y * ROWS_PER_SPLIT;

    // threads 0..127 compute h1[r0 + t] = relu(b1 + sum_k s[k]*W1[k][r0+t])
    if (t < ROWS_PER_SPLIT) {
        float acc = b1[r0 + t];
        #pragma unroll
        for (int k = 0; k < 42; k++)
            acc = fmaf(s[k], __ldg(W1 + (size_t)k * H + r0 + t), acc);
        xs[t] = fmaxf(acc, 0.0f);
    }
    __syncthreads();

    int c = (blockIdx.x * 256 + t) * 4;
    const float4* W = reinterpret_cast<const float4*>(W2 + (size_t)r0 * H + c);

    float4 acc = make_float4(0.f, 0.f, 0.f, 0.f);
    #pragma unroll
    for (int rb = 0; rb < ROWS_PER_SPLIT; rb += UNROLL) {
        // batch the loads first: 8 independent LDG.128 in flight per thread
        float4 w[UNROLL];
        #pragma unroll
        for (int u = 0; u < UNROLL; u++)
            w[u] = __ldcs(&W[(size_t)(rb + u) * (H / 4)]);
        #pragma unroll
        for (int u = 0; u < UNROLL; u++) {
            float x = xs[rb + u];
            acc.x = fmaf(x, w[u].x, acc.x);
            acc.y = fmaf(x, w[u].y, acc.y);
            acc.z = fmaf(x, w[u].z, acc.z);
            acc.w = fmaf(x, w[u].w, acc.w);
        }
    }
    *reinterpret_cast<float4*>(g_part + (size_t)blockIdx.y * H + c) = acc;
}

// ---------------- Fused: reduce partials -> h2 (in-register) -> pen partials ------
// 32 blocks x 256 threads: thread handles one column j of h2, then its W3 row.
__global__ void __launch_bounds__(256) k3_fused(const float* __restrict__ b2,
                                                const float* __restrict__ W3) {
    __shared__ float red[256][8];
    int t = threadIdx.x;
    int j = blockIdx.x * 256 + t;

    float acc = b2[j];
    #pragma unroll
    for (int sIdx = 0; sIdx < NSPLIT; sIdx++)
        acc += g_part[(size_t)sIdx * H + j];
    float h2 = fmaxf(acc, 0.0f);

    float4 w0 = *reinterpret_cast<const float4*>(W3 + (size_t)j * 8);
    float4 w1 = *reinterpret_cast<const float4*>(W3 + (size_t)j * 8 + 4);
    red[t][0] = h2 * w0.x;
    red[t][1] = h2 * w0.y;
    red[t][2] = h2 * w0.z;
    red[t][3] = h2 * w0.w;
    red[t][4] = h2 * w1.x;
    red[t][5] = h2 * w1.y;
    red[t][6] = h2 * w1.z;
    red[t][7] = h2 * w1.w;
    __syncthreads();

    for (int stride = 128; stride > 0; stride >>= 1) {
        if (t < stride) {
            #pragma unroll
            for (int n = 0; n < 8; n++) red[t][n] += red[t + stride][n];
        }
        __syncthreads();
    }

    if (t < 8) g_pen_part[blockIdx.x * 8 + t] = red[0][t];
}

// ---------------- Final: sum pen partials over 32 col-blocks, bias, softmax ------
__global__ void k_final(const float* __restrict__ state,
                        const float* __restrict__ b3,
                        float* __restrict__ out) {
    int t = threadIdx.x;   // one warp
    float pen = 0.0f;
    if (t < 8) {
        pen = b3[t];
        #pragma unroll
        for (int sIdx = 0; sIdx < 32; sIdx++)
            pen += g_pen_part[sIdx * 8 + t];
    }
    float pens[8];
    #pragma unroll
    for (int n = 0; n < 8; n++)
        pens[n] = __shfl_sync(0xFFFFFFFF, pen, n);

    if (t == 0) {
        float value = pens[7];
        bool legal[7];
        float mx = -INFINITY;
        #pragma unroll
        for (int n = 0; n < 7; n++) {
            legal[n] = (state[n] == 0.0f);
            if (legal[n] && pens[n] > mx) mx = pens[n];
        }
        float e[7];
        float sum = 0.0f;
        #pragma unroll
        for (int n = 0; n < 7; n++) {
            e[n] = legal[n] ? expf(pens[n] - mx) : 0.0f;
            sum += e[n];
        }
        float inv = 1.0f / sum;
        out[0] = value;
        #pragma unroll
        for (int n = 0; n < 7; n++) out[1 + n] = e[n] * inv;
    }
}

extern "C" void kernel_launch(void* const* d_in, const int* in_sizes, int n_in,
                              void* d_out, int out_size) {
    const float* state = (const float*)d_in[0];
    const float* W1    = (const float*)d_in[1];
    const float* b1    = (const float*)d_in[2];
    const float* W2    = (const float*)d_in[3];
    const float* b2    = (const float*)d_in[4];
    const float* W3    = (const float*)d_in[5];
    const float* b3    = (const float*)d_in[6];
    float* out = (float*)d_out;

    dim3 g2(COLBLKS, NSPLIT);   // (8, 64) = 512 blocks, single wave at 4 CTAs/SM
    k2_fused<<<g2, 256>>>(state, W1, b1, W2);

    k3_fused<<<32, 256>>>(b2, W3);   // 32 blocks x 256 = 8192 columns

    k_final<<<1, 32>>>(state, b3, out);
}

// round 5
// speedup vs baseline: 1.8709x; 1.2526x over previous
#include <cuda_runtime.h>
#include <math.h>

#define H 8192
#define NSPLIT 64
#define MAX_RPS 128                   // ceil(8192/64) worst case (fully dense)
#define COLBLKS (H / (256 * 4))       // 8
#define UNROLL 8

// Scratch (no cudaMalloc allowed)
__device__ float g_h1[H];
__device__ float g_xc[H];                // compacted nonzero h1 values
__device__ int   g_ic[H];                // their row indices
__device__ int   g_nnz;
__device__ float g_part[NSPLIT * H];     // layer-2 partials (2 MB, L2-resident)
__device__ float g_pen_part[32 * 8];     // head partials

// ---------------- k1: h1 = relu(state @ W1 + b1) ----------------
__global__ void __launch_bounds__(256) k1_layer1(const float* __restrict__ state,
                                                 const float* __restrict__ W1,
                                                 const float* __restrict__ b1) {
    __shared__ float s[42];
    int t = threadIdx.x;
    if (t < 42) s[t] = state[t];
    __syncthreads();
    int j = blockIdx.x * 256 + t;
    float acc = b1[j];
    #pragma unroll
    for (int k = 0; k < 42; k++)
        acc = fmaf(s[k], W1[(size_t)k * H + j], acc);
    g_h1[j] = fmaxf(acc, 0.0f);
}

// ---------------- k1b: deterministic compaction of nonzero h1 ----------------
// One block, 1024 threads, each owns 8 consecutive elements. Prefix-sum via
// warp shuffles + smem of warp totals. Order-preserving -> bit-deterministic.
__global__ void __launch_bounds__(1024) k1b_compact() {
    __shared__ int warp_tot[32];
    int t = threadIdx.x;
    int lane = t & 31, wid = t >> 5;

    float v[8];
    int base = t * 8;
    int cnt = 0;
    #pragma unroll
    for (int i = 0; i < 8; i++) {
        v[i] = g_h1[base + i];
        cnt += (v[i] > 0.0f);
    }

    // exclusive scan of cnt across 1024 threads
    int x = cnt;
    #pragma unroll
    for (int d = 1; d < 32; d <<= 1) {
        int y = __shfl_up_sync(0xFFFFFFFF, x, d);
        if (lane >= d) x += y;
    }
    if (lane == 31) warp_tot[wid] = x;          // inclusive warp total
    int excl = x - cnt;                          // exclusive within warp
    __syncthreads();
    if (wid == 0) {
        int w = (lane < 32) ? warp_tot[lane] : 0;
        #pragma unroll
        for (int d = 1; d < 32; d <<= 1) {
            int y = __shfl_up_sync(0xFFFFFFFF, w, d);
            if (lane >= d) w += y;
        }
        warp_tot[lane] = w;                      // inclusive scan of warp totals
    }
    __syncthreads();
    int offset = excl + (wid > 0 ? warp_tot[wid - 1] : 0);

    #pragma unroll
    for (int i = 0; i < 8; i++) {
        if (v[i] > 0.0f) {
            g_xc[offset] = v[i];
            g_ic[offset] = base + i;
            offset++;
        }
    }
    if (t == 1023) g_nnz = offset;               // grand total
}

// ---------------- k2: sparse split-K GEMV over gathered W2 rows ----------------
// blockIdx.x: column block (1024 cols via 256 thr * float4)
// blockIdx.y: split over the compacted nonzero rows
__global__ void __launch_bounds__(256, 4) k2_sparse(const float* __restrict__ W2) {
    __shared__ float xs[MAX_RPS];
    __shared__ int   ridx[MAX_RPS];
    int t = threadIdx.x;

    int nnz = g_nnz;
    int rps = (nnz + NSPLIT - 1) / NSPLIT;       // <= 128 by construction
    int rbeg = blockIdx.y * rps;
    int rend = min(rbeg + rps, nnz);
    int nr = rend - rbeg; if (nr < 0) nr = 0;

    if (t < nr) {
        xs[t]   = g_xc[rbeg + t];
        ridx[t] = g_ic[rbeg + t];
    }
    __syncthreads();

    int c = (blockIdx.x * 256 + t) * 4;
    float4 acc = make_float4(0.f, 0.f, 0.f, 0.f);

    int nr8 = nr & ~(UNROLL - 1);
    for (int rb = 0; rb < nr8; rb += UNROLL) {
        float4 w[UNROLL];
        #pragma unroll
        for (int u = 0; u < UNROLL; u++)
            w[u] = __ldcs(reinterpret_cast<const float4*>(
                       W2 + (size_t)ridx[rb + u] * H + c));
        #pragma unroll
        for (int u = 0; u < UNROLL; u++) {
            float xv = xs[rb + u];
            acc.x = fmaf(xv, w[u].x, acc.x);
            acc.y = fmaf(xv, w[u].y, acc.y);
            acc.z = fmaf(xv, w[u].z, acc.z);
            acc.w = fmaf(xv, w[u].w, acc.w);
        }
    }
    for (int r = nr8; r < nr; r++) {
        float4 w = __ldcs(reinterpret_cast<const float4*>(
                       W2 + (size_t)ridx[r] * H + c));
        float xv = xs[r];
        acc.x = fmaf(xv, w.x, acc.x);
        acc.y = fmaf(xv, w.y, acc.y);
        acc.z = fmaf(xv, w.z, acc.z);
        acc.w = fmaf(xv, w.w, acc.w);
    }
    *reinterpret_cast<float4*>(g_part + (size_t)blockIdx.y * H + c) = acc;
}

// ---------------- k3: reduce partials -> h2 -> pen partials (fused W3) ----------
__global__ void __launch_bounds__(256) k3_fused(const float* __restrict__ b2,
                                                const float* __restrict__ W3) {
    __shared__ float red[256][8];
    int t = threadIdx.x;
    int j = blockIdx.x * 256 + t;

    float acc = b2[j];
    #pragma unroll
    for (int sIdx = 0; sIdx < NSPLIT; sIdx++)
        acc += g_part[(size_t)sIdx * H + j];
    float h2 = fmaxf(acc, 0.0f);

    float4 w0 = *reinterpret_cast<const float4*>(W3 + (size_t)j * 8);
    float4 w1 = *reinterpret_cast<const float4*>(W3 + (size_t)j * 8 + 4);
    red[t][0] = h2 * w0.x;  red[t][1] = h2 * w0.y;
    red[t][2] = h2 * w0.z;  red[t][3] = h2 * w0.w;
    red[t][4] = h2 * w1.x;  red[t][5] = h2 * w1.y;
    red[t][6] = h2 * w1.z;  red[t][7] = h2 * w1.w;
    __syncthreads();

    for (int stride = 128; stride > 0; stride >>= 1) {
        if (t < stride) {
            #pragma unroll
            for (int n = 0; n < 8; n++) red[t][n] += red[t + stride][n];
        }
        __syncthreads();
    }
    if (t < 8) g_pen_part[blockIdx.x * 8 + t] = red[0][t];
}

// ---------------- k_final: bias, value + masked softmax ----------
__global__ void k_final(const float* __restrict__ state,
                        const float* __restrict__ b3,
                        float* __restrict__ out) {
    int t = threadIdx.x;   // one warp
    float pen = 0.0f;
    if (t < 8) {
        pen = b3[t];
        #pragma unroll
        for (int sIdx = 0; sIdx < 32; sIdx++)
            pen += g_pen_part[sIdx * 8 + t];
    }
    float pens[8];
    #pragma unroll
    for (int n = 0; n < 8; n++)
        pens[n] = __shfl_sync(0xFFFFFFFF, pen, n);

    if (t == 0) {
        float value = pens[7];
        bool legal[7];
        float mx = -INFINITY;
        #pragma unroll
        for (int n = 0; n < 7; n++) {
            legal[n] = (state[n] == 0.0f);
            if (legal[n] && pens[n] > mx) mx = pens[n];
        }
        float e[7];
        float sum = 0.0f;
        #pragma unroll
        for (int n = 0; n < 7; n++) {
            e[n] = legal[n] ? expf(pens[n] - mx) : 0.0f;
            sum += e[n];
        }
        float inv = 1.0f / sum;
        out[0] = value;
        #pragma unroll
        for (int n = 0; n < 7; n++) out[1 + n] = e[n] * inv;
    }
}

extern "C" void kernel_launch(void* const* d_in, const int* in_sizes, int n_in,
                              void* d_out, int out_size) {
    const float* state = (const float*)d_in[0];
    const float* W1    = (const float*)d_in[1];
    const float* b1    = (const float*)d_in[2];
    const float* W2    = (const float*)d_in[3];
    const float* b2    = (const float*)d_in[4];
    const float* W3    = (const float*)d_in[5];
    const float* b3    = (const float*)d_in[6];
    float* out = (float*)d_out;

    k1_layer1<<<H / 256, 256>>>(state, W1, b1);
    k1b_compact<<<1, 1024>>>();

    dim3 g2(COLBLKS, NSPLIT);   // (8, 64) = 512 blocks
    k2_sparse<<<g2, 256>>>(W2);

    k3_fused<<<32, 256>>>(b2, W3);
    k_final<<<1, 32>>>(state, b3, out);
}

// round 6
// speedup vs baseline: 2.2310x; 1.1925x over previous
#include <cuda_runtime.h>
#include <math.h>

#define H 8192
#define NSPLIT 64
#define ROWS_PER_SPLIT (H / NSPLIT)   // 128
#define COLBLKS (H / (256 * 4))       // 8
#define UNROLL 8
#define SGRP 8                         // splits per k3a group

// Scratch (no cudaMalloc allowed)
__device__ float g_part[NSPLIT * H];          // layer-2 partials (2 MB, L2)
__device__ float g_part2[(NSPLIT / SGRP) * H];// stage-2 partials (256 KB)
__device__ float g_pen_part[32 * 8];          // head partials

// ---- k2: fused h1-recompute + in-block sparse compaction + split-K GEMV ----
// blockIdx.x: column block (1024 cols via 256 thr * float4)
// blockIdx.y: row split (128 dense rows; only nonzero-h1 rows are gathered)
__global__ void __launch_bounds__(256, 4) k2_fused(const float* __restrict__ state,
                                                   const float* __restrict__ W1,
                                                   const float* __restrict__ b1,
                                                   const float* __restrict__ W2) {
    __shared__ float s[42];
    __shared__ float xs[ROWS_PER_SPLIT];
    __shared__ int   ridx[ROWS_PER_SPLIT];
    __shared__ int   wcnt[4];
    int t = threadIdx.x;
    int lane = t & 31, wid = t >> 5;
    if (t < 42) s[t] = state[t];
    __syncthreads();

    int r0 = blockIdx.y * ROWS_PER_SPLIT;

    // threads 0..127 (warps 0-3): compute h1[r0+t], then order-preserving compact
    float v = 0.0f;
    int pos = 0;
    if (t < ROWS_PER_SPLIT) {
        float acc = b1[r0 + t];
        #pragma unroll
        for (int k = 0; k < 42; k++)
            acc = fmaf(s[k], __ldg(W1 + (size_t)k * H + r0 + t), acc);
        v = fmaxf(acc, 0.0f);
        unsigned m = __ballot_sync(0xFFFFFFFF, v > 0.0f);
        pos = __popc(m & ((1u << lane) - 1));
        if (lane == 0) wcnt[wid] = __popc(m);
    }
    __syncthreads();
    int nr = wcnt[0] + wcnt[1] + wcnt[2] + wcnt[3];
    if (t < ROWS_PER_SPLIT && v > 0.0f) {
        int off = pos;
        for (int w = 0; w < 4; w++) if (w < wid) off += wcnt[w];
        xs[off]   = v;
        ridx[off] = r0 + t;
    }
    __syncthreads();

    int c = (blockIdx.x * 256 + t) * 4;
    float4 acc = make_float4(0.f, 0.f, 0.f, 0.f);

    int nr8 = nr & ~(UNROLL - 1);
    for (int rb = 0; rb < nr8; rb += UNROLL) {
        float4 w[UNROLL];
        #pragma unroll
        for (int u = 0; u < UNROLL; u++)
            w[u] = __ldcs(reinterpret_cast<const float4*>(
                       W2 + (size_t)ridx[rb + u] * H + c));
        #pragma unroll
        for (int u = 0; u < UNROLL; u++) {
            float xv = xs[rb + u];
            acc.x = fmaf(xv, w[u].x, acc.x);
            acc.y = fmaf(xv, w[u].y, acc.y);
            acc.z = fmaf(xv, w[u].z, acc.z);
            acc.w = fmaf(xv, w[u].w, acc.w);
        }
    }
    for (int r = nr8; r < nr; r++) {
        float4 w = __ldcs(reinterpret_cast<const float4*>(
                       W2 + (size_t)ridx[r] * H + c));
        float xv = xs[r];
        acc.x = fmaf(xv, w.x, acc.x);
        acc.y = fmaf(xv, w.y, acc.y);
        acc.z = fmaf(xv, w.z, acc.z);
        acc.w = fmaf(xv, w.w, acc.w);
    }
    *reinterpret_cast<float4*>(g_part + (size_t)blockIdx.y * H + c) = acc;
}

// ---- k3a: stage-1 reduce — 256 blocks, each sums SGRP=8 partials for 256 cols ----
__global__ void __launch_bounds__(256) k3a(void) {
    int t = threadIdx.x;
    int j = blockIdx.x * 256 + t;
    int g = blockIdx.y;                  // split group
    float a[SGRP];
    #pragma unroll
    for (int sIdx = 0; sIdx < SGRP; sIdx++)
        a[sIdx] = g_part[(size_t)(g * SGRP + sIdx) * H + j];
    float acc = 0.0f;
    #pragma unroll
    for (int sIdx = 0; sIdx < SGRP; sIdx++) acc += a[sIdx];
    g_part2[(size_t)g * H + j] = acc;
}

// ---- k3b: stage-2 reduce + bias + relu + fused W3 head partials ----
__global__ void __launch_bounds__(256) k3b(const float* __restrict__ b2,
                                           const float* __restrict__ W3) {
    __shared__ float red[256][8];
    int t = threadIdx.x;
    int j = blockIdx.x * 256 + t;

    float acc = b2[j];
    #pragma unroll
    for (int g = 0; g < NSPLIT / SGRP; g++)
        acc += g_part2[(size_t)g * H + j];
    float h2 = fmaxf(acc, 0.0f);

    float4 w0 = *reinterpret_cast<const float4*>(W3 + (size_t)j * 8);
    float4 w1 = *reinterpret_cast<const float4*>(W3 + (size_t)j * 8 + 4);
    red[t][0] = h2 * w0.x;  red[t][1] = h2 * w0.y;
    red[t][2] = h2 * w0.z;  red[t][3] = h2 * w0.w;
    red[t][4] = h2 * w1.x;  red[t][5] = h2 * w1.y;
    red[t][6] = h2 * w1.z;  red[t][7] = h2 * w1.w;
    __syncthreads();

    for (int stride = 128; stride > 0; stride >>= 1) {
        if (t < stride) {
            #pragma unroll
            for (int n = 0; n < 8; n++) red[t][n] += red[t + stride][n];
        }
        __syncthreads();
    }
    if (t < 8) g_pen_part[blockIdx.x * 8 + t] = red[0][t];
}

// ---- k_final: bias, value + masked softmax ----
__global__ void k_final(const float* __restrict__ state,
                        const float* __restrict__ b3,
                        float* __restrict__ out) {
    int t = threadIdx.x;   // one warp
    float pen = 0.0f;
    if (t < 8) {
        pen = b3[t];
        #pragma unroll
        for (int sIdx = 0; sIdx < 32; sIdx++)
            pen += g_pen_part[sIdx * 8 + t];
    }
    float pens[8];
    #pragma unroll
    for (int n = 0; n < 8; n++)
        pens[n] = __shfl_sync(0xFFFFFFFF, pen, n);

    if (t == 0) {
        float value = pens[7];
        bool legal[7];
        float mx = -INFINITY;
        #pragma unroll
        for (int n = 0; n < 7; n++) {
            legal[n] = (state[n] == 0.0f);
            if (legal[n] && pens[n] > mx) mx = pens[n];
        }
        float e[7];
        float sum = 0.0f;
        #pragma unroll
        for (int n = 0; n < 7; n++) {
            e[n] = legal[n] ? expf(pens[n] - mx) : 0.0f;
            sum += e[n];
        }
        float inv = 1.0f / sum;
        out[0] = value;
        #pragma unroll
        for (int n = 0; n < 7; n++) out[1 + n] = e[n] * inv;
    }
}

extern "C" void kernel_launch(void* const* d_in, const int* in_sizes, int n_in,
                              void* d_out, int out_size) {
    const float* state = (const float*)d_in[0];
    const float* W1    = (const float*)d_in[1];
    const float* b1    = (const float*)d_in[2];
    const float* W2    = (const float*)d_in[3];
    const float* b2    = (const float*)d_in[4];
    const float* W3    = (const float*)d_in[5];
    const float* b3    = (const float*)d_in[6];
    float* out = (float*)d_out;

    dim3 g2(COLBLKS, NSPLIT);             // (8, 64) = 512 blocks
    k2_fused<<<g2, 256>>>(state, W1, b1, W2);

    dim3 g3(32, NSPLIT / SGRP);           // (32, 8) = 256 blocks
    k3a<<<g3, 256>>>();

    k3b<<<32, 256>>>(b2, W3);
    k_final<<<1, 32>>>(state, b3, out);
}